// round 2
// baseline (speedup 1.0000x reference)
#include <cuda_runtime.h>

// Problem constants
namespace {
constexpr int B   = 2;
constexpr int S   = 2048;
constexpr int DIN = 1024;
constexpr int H   = 16;
constexpr int E   = 64;

// projection tiles
constexpr int TS = 64;   // rows of x per block
constexpr int TK = 32;   // d-chunk

// attention tiles
constexpr int QR = 128;  // query rows per block (1 thread per row)
constexpr int KT = 32;   // key rows per smem tile
}

// Scratch for Q/K/V in [B,H,S,E] layout (16 MB each). __device__ globals are the
// allowed alloc-free scratch mechanism.
__device__ float g_q[(size_t)B * H * S * E];
__device__ float g_k[(size_t)B * H * S * E];
__device__ float g_v[(size_t)B * H * S * E];

// ---------------------------------------------------------------------------
// Kernel 1: fused QKV projection.
// grid = (S/TS, H, B), block = 256.
// Each block computes a [TS=64, E=64] output tile for q, k and v of one head,
// reusing the x tile (loaded once per d-chunk) for all three weight matrices.
// Per thread: 4x4 micro-tile for each of q/k/v (48 accumulators).
// ---------------------------------------------------------------------------
__global__ __launch_bounds__(256) void qkv_proj_kernel(
    const float* __restrict__ x,
    const float* __restrict__ Wq,
    const float* __restrict__ Wk,
    const float* __restrict__ Wv) {
  __shared__ float xs[TK][TS + 1];   // x tile, transposed [k][s], padded
  __shared__ float ws[3][TK][E];     // wq/wk/wv chunks [k][e]

  const int st  = blockIdx.x;
  const int h   = blockIdx.y;
  const int b   = blockIdx.z;
  const int tid = threadIdx.x;
  const int tc  = tid & 15;   // column group: cols [4*tc, 4*tc+3]
  const int tr  = tid >> 4;   // row group:    rows [4*tr, 4*tr+3]

  float acc[3][4][4];
#pragma unroll
  for (int w = 0; w < 3; w++)
#pragma unroll
    for (int i = 0; i < 4; i++)
#pragma unroll
      for (int j = 0; j < 4; j++) acc[w][i][j] = 0.f;

  const float* xb  = x  + ((size_t)b * S + (size_t)st * TS) * DIN;
  const float* wb0 = Wq + (size_t)h * DIN * E;
  const float* wb1 = Wk + (size_t)h * DIN * E;
  const float* wb2 = Wv + (size_t)h * DIN * E;

  for (int k0 = 0; k0 < DIN; k0 += TK) {
    __syncthreads();
    // load x tile (64 rows x 32 cols) transposed into xs[k][s]
    for (int f = tid; f < (TS * TK / 4); f += 256) {
      int r  = f >> 3;       // row in [0,64)
      int c4 = f & 7;        // float4 index in [0,8)
      float4 xv = *(const float4*)(xb + (size_t)r * DIN + k0 + c4 * 4);
      xs[c4 * 4 + 0][r] = xv.x;
      xs[c4 * 4 + 1][r] = xv.y;
      xs[c4 * 4 + 2][r] = xv.z;
      xs[c4 * 4 + 3][r] = xv.w;
    }
    // load the three 32x64 weight chunks
    {
      const float* wp0 = wb0 + (size_t)k0 * E;
      const float* wp1 = wb1 + (size_t)k0 * E;
      const float* wp2 = wb2 + (size_t)k0 * E;
      for (int f = tid; f < (TK * E / 4); f += 256) {
        int r  = f >> 4;   // row in [0,32)
        int c4 = f & 15;   // float4 index in [0,16)
        *(float4*)&ws[0][r][c4 * 4] = *(const float4*)(wp0 + (size_t)r * E + c4 * 4);
        *(float4*)&ws[1][r][c4 * 4] = *(const float4*)(wp1 + (size_t)r * E + c4 * 4);
        *(float4*)&ws[2][r][c4 * 4] = *(const float4*)(wp2 + (size_t)r * E + c4 * 4);
      }
    }
    __syncthreads();

#pragma unroll
    for (int kk = 0; kk < TK; kk++) {
      float xv[4];
#pragma unroll
      for (int i = 0; i < 4; i++) xv[i] = xs[kk][tr * 4 + i];
#pragma unroll
      for (int w = 0; w < 3; w++) {
        float4 wv = *(const float4*)&ws[w][kk][tc * 4];
#pragma unroll
        for (int i = 0; i < 4; i++) {
          acc[w][i][0] += xv[i] * wv.x;
          acc[w][i][1] += xv[i] * wv.y;
          acc[w][i][2] += xv[i] * wv.z;
          acc[w][i][3] += xv[i] * wv.w;
        }
      }
    }
  }

  // store results to [B,H,S,E] scratch
  const size_t base = ((size_t)b * H + h) * S + (size_t)st * TS;
  float* outs[3] = {g_q, g_k, g_v};
#pragma unroll
  for (int w = 0; w < 3; w++) {
#pragma unroll
    for (int i = 0; i < 4; i++) {
      float4 ov = make_float4(acc[w][i][0], acc[w][i][1], acc[w][i][2], acc[w][i][3]);
      *(float4*)(outs[w] + (base + tr * 4 + i) * E + tc * 4) = ov;
    }
  }
}

// ---------------------------------------------------------------------------
// Kernel 2: causal flash attention, fp32, online softmax.
// grid = (S/QR, H, B), block = QR (one thread per query row).
// Key/value tiles of KT=32 rows staged in smem; smem reads are warp-broadcast
// float4 loads (conflict-free). Causal early exit: only tiles up to the query
// block's diagonal are visited; per-element mask applied near the diagonal.
// ---------------------------------------------------------------------------
__global__ __launch_bounds__(QR) void attn_kernel(float* __restrict__ out) {
  __shared__ float Ks[KT][E];
  __shared__ float Vs[KT][E];

  const int qt  = blockIdx.x;
  const int h   = blockIdx.y;
  const int b   = blockIdx.z;
  const int row = qt * QR + threadIdx.x;

  const size_t head_base = (((size_t)b * H + h) * S) * E;
  const float* qp = g_q + head_base + (size_t)row * E;
  const float* kb = g_k + head_base;
  const float* vb = g_v + head_base;

  float4 qr[E / 4];
#pragma unroll
  for (int e4 = 0; e4 < E / 4; e4++) qr[e4] = ((const float4*)qp)[e4];

  float4 o[E / 4];
#pragma unroll
  for (int e4 = 0; e4 < E / 4; e4++) o[e4] = make_float4(0.f, 0.f, 0.f, 0.f);

  float m = -1e30f;
  float l = 0.f;
  const float scale = 0.125f;  // 1/sqrt(E=64)

  const int kmax = qt * QR + (QR - 1);  // last key this block can attend to

  for (int j0 = 0; j0 <= kmax; j0 += KT) {
    __syncthreads();
    // cooperative load of K/V tiles (KT x E floats each), fully coalesced
    for (int f = threadIdx.x; f < KT * E / 4; f += QR) {
      int r  = f >> 4;
      int c4 = f & 15;
      ((float4*)&Ks[r][0])[c4] = ((const float4*)(kb + (size_t)(j0 + r) * E))[c4];
      ((float4*)&Vs[r][0])[c4] = ((const float4*)(vb + (size_t)(j0 + r) * E))[c4];
    }
    __syncthreads();

    float sc[KT];
    float tmax = -1e30f;
#pragma unroll
    for (int j = 0; j < KT; j++) {
      const float4* kr = (const float4*)&Ks[j][0];
      float s0 = 0.f, s1 = 0.f, s2 = 0.f, s3 = 0.f;
#pragma unroll
      for (int e4 = 0; e4 < E / 4; e4++) {
        float4 kv = kr[e4];
        s0 += qr[e4].x * kv.x;
        s1 += qr[e4].y * kv.y;
        s2 += qr[e4].z * kv.z;
        s3 += qr[e4].w * kv.w;
      }
      float s = ((s0 + s1) + (s2 + s3)) * scale;
      if (j0 + j > row) s = -1e30f;  // causal mask
      sc[j] = s;
      tmax  = fmaxf(tmax, s);
    }

    float mnew = fmaxf(m, tmax);
    float corr = __expf(m - mnew);
    l *= corr;
#pragma unroll
    for (int e4 = 0; e4 < E / 4; e4++) {
      o[e4].x *= corr; o[e4].y *= corr; o[e4].z *= corr; o[e4].w *= corr;
    }

#pragma unroll
    for (int j = 0; j < KT; j++) {
      float p = __expf(sc[j] - mnew);
      l += p;
      const float4* vr = (const float4*)&Vs[j][0];
#pragma unroll
      for (int e4 = 0; e4 < E / 4; e4++) {
        float4 vv = vr[e4];
        o[e4].x += p * vv.x;
        o[e4].y += p * vv.y;
        o[e4].z += p * vv.z;
        o[e4].w += p * vv.w;
      }
    }
    m = mnew;
  }

  const float inv = 1.f / l;
  // output layout: [B, S, H*E]
  float* op = out + ((size_t)b * S + row) * (H * E) + (size_t)h * E;
#pragma unroll
  for (int e4 = 0; e4 < E / 4; e4++) {
    float4 ov = make_float4(o[e4].x * inv, o[e4].y * inv, o[e4].z * inv, o[e4].w * inv);
    ((float4*)op)[e4] = ov;
  }
}

// ---------------------------------------------------------------------------
// Harness entry
// ---------------------------------------------------------------------------
extern "C" void kernel_launch(void* const* d_in, const int* in_sizes, int n_in,
                              void* d_out, int out_size) {
  const float* x  = (const float*)d_in[0];
  const float* Wq = (const float*)d_in[1];
  const float* Wk = (const float*)d_in[2];
  const float* Wv = (const float*)d_in[3];
  float* out = (float*)d_out;

  dim3 g1(S / TS, H, B);
  qkv_proj_kernel<<<g1, 256>>>(x, Wq, Wk, Wv);

  dim3 g2(S / QR, H, B);
  attn_kernel<<<g2, QR>>>(out);
}

// round 3
// speedup vs baseline: 2.9424x; 2.9424x over previous
#include <cuda_runtime.h>
#include <cstdint>

// Problem constants
namespace {
constexpr int B   = 2;
constexpr int S   = 2048;
constexpr int DIN = 1024;
constexpr int H   = 16;
constexpr int E   = 64;

constexpr int QR = 128;  // query rows per attention block
constexpr int KT = 64;   // key tile
}

// Q/K/V scratch, [B,H,S,E]
__device__ float g_q[(size_t)B * H * S * E];
__device__ float g_k[(size_t)B * H * S * E];
__device__ float g_v[(size_t)B * H * S * E];

// ---------------------------------------------------------------------------
// tf32 helpers (m16n8k8 row.col, fp32 accumulate)
// A frag (16x8):  a0=A[g][t4]  a1=A[g+8][t4]  a2=A[g][t4+4]  a3=A[g+8][t4+4]
// B frag (8x8):   b0=B[t4][g]  b1=B[t4+4][g]          (B is KxN)
// C frag (16x8):  c0=C[g][2t4] c1=C[g][2t4+1] c2=C[g+8][2t4] c3=C[g+8][2t4+1]
// with g = lane>>2, t4 = lane&3
// ---------------------------------------------------------------------------
__device__ __forceinline__ uint32_t f2tf32(float x) {
  uint32_t r;
  asm("cvt.rna.tf32.f32 %0, %1;" : "=r"(r) : "f"(x));
  return r;
}

__device__ __forceinline__ void mma_tf32(float c[4], const uint32_t a[4],
                                         uint32_t b0, uint32_t b1) {
  asm volatile(
      "mma.sync.aligned.m16n8k8.row.col.f32.tf32.tf32.f32 "
      "{%0,%1,%2,%3}, {%4,%5,%6,%7}, {%8,%9}, {%0,%1,%2,%3};"
      : "+f"(c[0]), "+f"(c[1]), "+f"(c[2]), "+f"(c[3])
      : "r"(a[0]), "r"(a[1]), "r"(a[2]), "r"(a[3]), "r"(b0), "r"(b1));
}

// ---------------------------------------------------------------------------
// Kernel 1: fused QKV projection, tf32 MMA.
// grid=(S/64, H, B), block=384 (12 warps). Warp w: output matrix (w%3) in
// {q,k,v}, row block (w/3) of 16 rows; each warp computes 16x64 per K chunk.
// ---------------------------------------------------------------------------
__global__ __launch_bounds__(384) void qkv_proj_mma(
    const float* __restrict__ x,
    const float* __restrict__ Wq,
    const float* __restrict__ Wk,
    const float* __restrict__ Wv) {
  __shared__ __align__(16) uint32_t Xs[64][36];      // x tile, tf32, [row][k]
  __shared__ __align__(16) uint32_t Ws[3][64][36];   // W^T tiles, tf32, [n][k]

  const int st   = blockIdx.x;
  const int h    = blockIdx.y;
  const int b    = blockIdx.z;
  const int tid  = threadIdx.x;
  const int warp = tid >> 5;
  const int lane = tid & 31;
  const int g    = lane >> 2;
  const int t4   = lane & 3;
  const int om   = warp % 3;   // 0=q 1=k 2=v
  const int rb   = warp / 3;   // 0..3

  float co[8][4];
#pragma unroll
  for (int nt = 0; nt < 8; nt++)
#pragma unroll
    for (int i = 0; i < 4; i++) co[nt][i] = 0.f;

  const float* xb = x + ((size_t)b * S + (size_t)st * 64) * DIN;
  // weight source for the smem-fill role of this thread
  const int lom = tid >> 7;  // 0..2
  const float* wsrc =
      ((lom == 0) ? Wq : (lom == 1) ? Wk : Wv) + (size_t)h * DIN * E;
  const int lrr = tid & 127;
  const int ln  = lrr & 63;
  const int lk4 = lrr >> 6;  // 0..1

  for (int k0 = 0; k0 < DIN; k0 += 32) {
    __syncthreads();
    // stage X tile (64 rows x 32 k), tf32
    if (tid < 256) {
#pragma unroll
      for (int i = 0; i < 2; i++) {
        int f  = tid + 256 * i;
        int r  = f >> 3;
        int c4 = f & 7;
        float4 xv = *(const float4*)(xb + (size_t)r * DIN + k0 + c4 * 4);
        uint4 u = make_uint4(f2tf32(xv.x), f2tf32(xv.y), f2tf32(xv.z), f2tf32(xv.w));
        *(uint4*)&Xs[r][c4 * 4] = u;
      }
    }
    // stage W^T tiles [n][k] (transpose on store), tf32
    {
      const float* wp = wsrc + (size_t)k0 * E;
#pragma unroll
      for (int kk = 0; kk < 4; kk++) {
        int k4 = lk4 + 2 * kk;           // 0..7
        float w0 = wp[(size_t)(4 * k4 + 0) * E + ln];
        float w1 = wp[(size_t)(4 * k4 + 1) * E + ln];
        float w2 = wp[(size_t)(4 * k4 + 2) * E + ln];
        float w3 = wp[(size_t)(4 * k4 + 3) * E + ln];
        uint4 u = make_uint4(f2tf32(w0), f2tf32(w1), f2tf32(w2), f2tf32(w3));
        *(uint4*)&Ws[lom][ln][4 * k4] = u;
      }
    }
    __syncthreads();

#pragma unroll
    for (int ks = 0; ks < 4; ks++) {
      uint32_t a[4];
      a[0] = Xs[16 * rb + g][8 * ks + t4];
      a[1] = Xs[16 * rb + g + 8][8 * ks + t4];
      a[2] = Xs[16 * rb + g][8 * ks + t4 + 4];
      a[3] = Xs[16 * rb + g + 8][8 * ks + t4 + 4];
#pragma unroll
      for (int nt = 0; nt < 8; nt++) {
        uint32_t b0 = Ws[om][8 * nt + g][8 * ks + t4];
        uint32_t b1 = Ws[om][8 * nt + g][8 * ks + t4 + 4];
        mma_tf32(co[nt], a, b0, b1);
      }
    }
  }

  float* dst = (om == 0) ? g_q : (om == 1) ? g_k : g_v;
  const size_t rowbase = ((size_t)b * H + h) * S + (size_t)st * 64 + 16 * rb;
#pragma unroll
  for (int nt = 0; nt < 8; nt++) {
    int col = 8 * nt + 2 * t4;
    *(float2*)&dst[(rowbase + g) * E + col]     = make_float2(co[nt][0], co[nt][1]);
    *(float2*)&dst[(rowbase + g + 8) * E + col] = make_float2(co[nt][2], co[nt][3]);
  }
}

// ---------------------------------------------------------------------------
// Kernel 2: causal flash attention, tf32 MMA, fp32 softmax.
// grid=(S/QR, H, B) with qt reversed (heavy blocks first), block=256 (8 warps).
// Warp w owns query rows [16w, 16w+16) of the 128-row tile, so all row-wise
// softmax reductions stay within the warp's 4-lane groups.
// ---------------------------------------------------------------------------
__global__ __launch_bounds__(256) void attn_mma_kernel(float* __restrict__ out) {
  // smem union: Q staging [128][68] (8704 u32)  /  K^T [64][72] + V [64][72] (9216 u32)
  __shared__ __align__(16) uint32_t sbuf[9216];
  uint32_t (*Qs)[68]  = (uint32_t(*)[68])sbuf;
  uint32_t (*Kst)[72] = (uint32_t(*)[72])sbuf;            // [e][key]
  uint32_t (*Vs)[72]  = (uint32_t(*)[72])(sbuf + 64 * 72); // [key][e]

  const int qt   = (gridDim.x - 1) - blockIdx.x;
  const int h    = blockIdx.y;
  const int b    = blockIdx.z;
  const int tid  = threadIdx.x;
  const int warp = tid >> 5;
  const int lane = tid & 31;
  const int g    = lane >> 2;
  const int t4   = lane & 3;

  const size_t head_base = (((size_t)b * H + h) * S) * E;
  const float* kb = g_k + head_base;
  const float* vb = g_v + head_base;

  // ---- stage Q tile (scaled by 1/8), extract A fragments ----
  {
    const float* qsrc = g_q + head_base + (size_t)qt * QR * E;
#pragma unroll
    for (int i = 0; i < 8; i++) {
      int f  = tid + 256 * i;
      int r  = f >> 4;
      int c4 = f & 15;
      float4 qv = *(const float4*)(qsrc + (size_t)r * E + c4 * 4);
      uint4 u = make_uint4(f2tf32(qv.x * 0.125f), f2tf32(qv.y * 0.125f),
                           f2tf32(qv.z * 0.125f), f2tf32(qv.w * 0.125f));
      *(uint4*)&Qs[r][c4 * 4] = u;
    }
  }
  __syncthreads();

  uint32_t qa[8][4];
  {
    const int r0 = warp * 16 + g;
#pragma unroll
    for (int ks = 0; ks < 8; ks++) {
      qa[ks][0] = Qs[r0][8 * ks + t4];
      qa[ks][1] = Qs[r0 + 8][8 * ks + t4];
      qa[ks][2] = Qs[r0][8 * ks + t4 + 4];
      qa[ks][3] = Qs[r0 + 8][8 * ks + t4 + 4];
    }
  }

  // ---- online softmax state ----
  float o[8][4];
#pragma unroll
  for (int nt = 0; nt < 8; nt++)
#pragma unroll
    for (int i = 0; i < 4; i++) o[nt][i] = 0.f;
  float m0 = -1e30f, m1 = -1e30f, l0 = 0.f, l1 = 0.f;

  const int qrow0w   = qt * QR + warp * 16;  // warp's first query row
  const int rowmax_w = qrow0w + 15;
  const int rg  = qrow0w + g;
  const int rg8 = rg + 8;
  const int kend = (qt + 1) * QR;

  // K load role: e fixed, 4-key column segments
  const int le  = tid & 63;
  const int lj4 = tid >> 6;  // 0..3
  // V load role: row fixed, 4-e segments
  const int vj  = tid >> 2;
  const int ve4 = tid & 3;

  for (int j0 = 0; j0 < kend; j0 += KT) {
    __syncthreads();  // smem reuse barrier (also covers the Q->KV transition)
    // ---- stage K^T [e][key] ----
#pragma unroll
    for (int i = 0; i < 4; i++) {
      int jj4 = lj4 + 4 * i;  // 0..15
      const float* kp = kb + ((size_t)(j0 + 4 * jj4)) * E + le;
      uint4 u = make_uint4(f2tf32(kp[0]), f2tf32(kp[E]), f2tf32(kp[2 * E]),
                           f2tf32(kp[3 * E]));
      *(uint4*)&Kst[le][4 * jj4] = u;
    }
    // ---- stage V [key][e] ----
#pragma unroll
    for (int i = 0; i < 4; i++) {
      int e4 = ve4 + 4 * i;  // 0..15
      float4 vv = *(const float4*)(vb + ((size_t)(j0 + vj)) * E + 4 * e4);
      uint4 u = make_uint4(f2tf32(vv.x), f2tf32(vv.y), f2tf32(vv.z), f2tf32(vv.w));
      *(uint4*)&Vs[vj][4 * e4] = u;
    }
    __syncthreads();

    if (j0 > rowmax_w) continue;  // fully masked for this warp (warp-uniform)

    // ---- S = Q K^T (warp: 16 rows x 64 keys) ----
    float sc[8][4];
#pragma unroll
    for (int nt = 0; nt < 8; nt++)
#pragma unroll
      for (int i = 0; i < 4; i++) sc[nt][i] = 0.f;
#pragma unroll
    for (int ks = 0; ks < 8; ks++) {
#pragma unroll
      for (int nt = 0; nt < 8; nt++) {
        uint32_t b0 = Kst[8 * ks + t4][8 * nt + g];
        uint32_t b1 = Kst[8 * ks + t4 + 4][8 * nt + g];
        mma_tf32(sc[nt], qa[ks], b0, b1);
      }
    }

    // ---- causal mask (only near the diagonal) ----
    if (j0 + KT - 1 > qrow0w) {
      const int colb = j0 + 2 * t4;
#pragma unroll
      for (int nt = 0; nt < 8; nt++) {
        int c0 = colb + 8 * nt;
        if (c0 > rg)      sc[nt][0] = -1e30f;
        if (c0 + 1 > rg)  sc[nt][1] = -1e30f;
        if (c0 > rg8)     sc[nt][2] = -1e30f;
        if (c0 + 1 > rg8) sc[nt][3] = -1e30f;
      }
    }

    // ---- online softmax update ----
    float mx0 = -1e30f, mx1 = -1e30f;
#pragma unroll
    for (int nt = 0; nt < 8; nt++) {
      mx0 = fmaxf(mx0, fmaxf(sc[nt][0], sc[nt][1]));
      mx1 = fmaxf(mx1, fmaxf(sc[nt][2], sc[nt][3]));
    }
    mx0 = fmaxf(mx0, __shfl_xor_sync(0xffffffffu, mx0, 1));
    mx0 = fmaxf(mx0, __shfl_xor_sync(0xffffffffu, mx0, 2));
    mx1 = fmaxf(mx1, __shfl_xor_sync(0xffffffffu, mx1, 1));
    mx1 = fmaxf(mx1, __shfl_xor_sync(0xffffffffu, mx1, 2));

    float mn0 = fmaxf(m0, mx0), mn1 = fmaxf(m1, mx1);
    float corr0 = __expf(m0 - mn0), corr1 = __expf(m1 - mn1);
    m0 = mn0; m1 = mn1;

    float rs0 = 0.f, rs1 = 0.f;
#pragma unroll
    for (int nt = 0; nt < 8; nt++) {
      sc[nt][0] = __expf(sc[nt][0] - mn0);
      sc[nt][1] = __expf(sc[nt][1] - mn0);
      sc[nt][2] = __expf(sc[nt][2] - mn1);
      sc[nt][3] = __expf(sc[nt][3] - mn1);
      rs0 += sc[nt][0] + sc[nt][1];
      rs1 += sc[nt][2] + sc[nt][3];
    }
    l0 = l0 * corr0 + rs0;
    l1 = l1 * corr1 + rs1;
#pragma unroll
    for (int nt = 0; nt < 8; nt++) {
      o[nt][0] *= corr0; o[nt][1] *= corr0;
      o[nt][2] *= corr1; o[nt][3] *= corr1;
    }

    // ---- O += P V ----
    const int s0l = (lane & ~3) | (t4 >> 1);
    const int s2l = s0l + 2;
    const bool odd = (t4 & 1);
#pragma unroll
    for (int ks = 0; ks < 8; ks++) {
      // transpose P chunk (cols 8ks..8ks+7) from C-layout to A-layout
      float v00 = __shfl_sync(0xffffffffu, sc[ks][0], s0l);
      float v01 = __shfl_sync(0xffffffffu, sc[ks][1], s0l);
      float v02 = __shfl_sync(0xffffffffu, sc[ks][2], s0l);
      float v03 = __shfl_sync(0xffffffffu, sc[ks][3], s0l);
      float v20 = __shfl_sync(0xffffffffu, sc[ks][0], s2l);
      float v21 = __shfl_sync(0xffffffffu, sc[ks][1], s2l);
      float v22 = __shfl_sync(0xffffffffu, sc[ks][2], s2l);
      float v23 = __shfl_sync(0xffffffffu, sc[ks][3], s2l);
      uint32_t a[4];
      a[0] = f2tf32(odd ? v01 : v00);
      a[1] = f2tf32(odd ? v03 : v02);
      a[2] = f2tf32(odd ? v21 : v20);
      a[3] = f2tf32(odd ? v23 : v22);
#pragma unroll
      for (int nt = 0; nt < 8; nt++) {
        uint32_t b0 = Vs[8 * ks + t4][8 * nt + g];
        uint32_t b1 = Vs[8 * ks + t4 + 4][8 * nt + g];
        mma_tf32(o[nt], a, b0, b1);
      }
    }
  }

  // ---- finalize: reduce l across 4-lane group, normalize, write [B,S,H*E] ----
  l0 += __shfl_xor_sync(0xffffffffu, l0, 1);
  l0 += __shfl_xor_sync(0xffffffffu, l0, 2);
  l1 += __shfl_xor_sync(0xffffffffu, l1, 1);
  l1 += __shfl_xor_sync(0xffffffffu, l1, 2);
  const float inv0 = 1.f / l0;
  const float inv1 = 1.f / l1;

  float* op0 = out + ((size_t)b * S + rg) * (H * E) + (size_t)h * E;
  float* op8 = out + ((size_t)b * S + rg8) * (H * E) + (size_t)h * E;
#pragma unroll
  for (int nt = 0; nt < 8; nt++) {
    int col = 8 * nt + 2 * t4;
    *(float2*)&op0[col] = make_float2(o[nt][0] * inv0, o[nt][1] * inv0);
    *(float2*)&op8[col] = make_float2(o[nt][2] * inv1, o[nt][3] * inv1);
  }
}

// ---------------------------------------------------------------------------
extern "C" void kernel_launch(void* const* d_in, const int* in_sizes, int n_in,
                              void* d_out, int out_size) {
  const float* x  = (const float*)d_in[0];
  const float* Wq = (const float*)d_in[1];
  const float* Wk = (const float*)d_in[2];
  const float* Wv = (const float*)d_in[3];
  float* out = (float*)d_out;

  dim3 g1(S / 64, H, B);
  qkv_proj_mma<<<g1, 384>>>(x, Wq, Wk, Wv);

  dim3 g2(S / QR, H, B);
  attn_mma_kernel<<<g2, 256>>>(out);
}

// round 4
// speedup vs baseline: 2.9602x; 1.0060x over previous
#include <cuda_runtime.h>
#include <cstdint>

// Problem constants
namespace {
constexpr int B   = 2;
constexpr int S   = 2048;
constexpr int DIN = 1024;
constexpr int H   = 16;
constexpr int E   = 64;

constexpr int QR = 128;  // query rows per attention block
constexpr int KT = 64;   // key tile
}

// Q/K/V scratch, [B,H,S,E]
__device__ float g_q[(size_t)B * H * S * E];
__device__ float g_k[(size_t)B * H * S * E];
__device__ float g_v[(size_t)B * H * S * E];

// ---------------------------------------------------------------------------
// tf32 helpers (m16n8k8 row.col, fp32 accumulate)
// A frag (16x8):  a0=A[g][t4]  a1=A[g+8][t4]  a2=A[g][t4+4]  a3=A[g+8][t4+4]
// B frag (8x8):   b0=B[t4][g]  b1=B[t4+4][g]          (B is KxN)
// C frag (16x8):  c0=C[g][2t4] c1=C[g][2t4+1] c2=C[g+8][2t4] c3=C[g+8][2t4+1]
// with g = lane>>2, t4 = lane&3
// ---------------------------------------------------------------------------
__device__ __forceinline__ uint32_t f2tf32(float x) {
  uint32_t r;
  asm("cvt.rna.tf32.f32 %0, %1;" : "=r"(r) : "f"(x));
  return r;
}

__device__ __forceinline__ void mma_tf32(float c[4], const uint32_t a[4],
                                         uint32_t b0, uint32_t b1) {
  asm volatile(
      "mma.sync.aligned.m16n8k8.row.col.f32.tf32.tf32.f32 "
      "{%0,%1,%2,%3}, {%4,%5,%6,%7}, {%8,%9}, {%0,%1,%2,%3};"
      : "+f"(c[0]), "+f"(c[1]), "+f"(c[2]), "+f"(c[3])
      : "r"(a[0]), "r"(a[1]), "r"(a[2]), "r"(a[3]), "r"(b0), "r"(b1));
}

// ---------------------------------------------------------------------------
// Kernel 1: fused QKV projection, tf32 MMA.
// grid=(S/64, H, B), block=384 (12 warps). Warp w: output matrix (w%3) in
// {q,k,v}, row block (w/3) of 16 rows; each warp computes 16x64 per K chunk.
// ---------------------------------------------------------------------------
__global__ __launch_bounds__(384) void qkv_proj_mma(
    const float* __restrict__ x,
    const float* __restrict__ Wq,
    const float* __restrict__ Wk,
    const float* __restrict__ Wv) {
  __shared__ __align__(16) uint32_t Xs[64][36];      // x tile, tf32, [row][k]
  __shared__ __align__(16) uint32_t Ws[3][64][36];   // W^T tiles, tf32, [n][k]

  const int st   = blockIdx.x;
  const int h    = blockIdx.y;
  const int b    = blockIdx.z;
  const int tid  = threadIdx.x;
  const int warp = tid >> 5;
  const int lane = tid & 31;
  const int g    = lane >> 2;
  const int t4   = lane & 3;
  const int om   = warp % 3;   // 0=q 1=k 2=v
  const int rb   = warp / 3;   // 0..3

  float co[8][4];
#pragma unroll
  for (int nt = 0; nt < 8; nt++)
#pragma unroll
    for (int i = 0; i < 4; i++) co[nt][i] = 0.f;

  const float* xb = x + ((size_t)b * S + (size_t)st * 64) * DIN;
  // weight source for the smem-fill role of this thread
  const int lom = tid >> 7;  // 0..2
  const float* wsrc =
      ((lom == 0) ? Wq : (lom == 1) ? Wk : Wv) + (size_t)h * DIN * E;
  const int lrr = tid & 127;
  const int ln  = lrr & 63;
  const int lk4 = lrr >> 6;  // 0..1

  for (int k0 = 0; k0 < DIN; k0 += 32) {
    __syncthreads();
    // stage X tile (64 rows x 32 k), tf32
    if (tid < 256) {
#pragma unroll
      for (int i = 0; i < 2; i++) {
        int f  = tid + 256 * i;
        int r  = f >> 3;
        int c4 = f & 7;
        float4 xv = *(const float4*)(xb + (size_t)r * DIN + k0 + c4 * 4);
        uint4 u = make_uint4(f2tf32(xv.x), f2tf32(xv.y), f2tf32(xv.z), f2tf32(xv.w));
        *(uint4*)&Xs[r][c4 * 4] = u;
      }
    }
    // stage W^T tiles [n][k] (transpose on store), tf32
    {
      const float* wp = wsrc + (size_t)k0 * E;
#pragma unroll
      for (int kk = 0; kk < 4; kk++) {
        int k4 = lk4 + 2 * kk;           // 0..7
        float w0 = wp[(size_t)(4 * k4 + 0) * E + ln];
        float w1 = wp[(size_t)(4 * k4 + 1) * E + ln];
        float w2 = wp[(size_t)(4 * k4 + 2) * E + ln];
        float w3 = wp[(size_t)(4 * k4 + 3) * E + ln];
        uint4 u = make_uint4(f2tf32(w0), f2tf32(w1), f2tf32(w2), f2tf32(w3));
        *(uint4*)&Ws[lom][ln][4 * k4] = u;
      }
    }
    __syncthreads();

#pragma unroll
    for (int ks = 0; ks < 4; ks++) {
      uint32_t a[4];
      a[0] = Xs[16 * rb + g][8 * ks + t4];
      a[1] = Xs[16 * rb + g + 8][8 * ks + t4];
      a[2] = Xs[16 * rb + g][8 * ks + t4 + 4];
      a[3] = Xs[16 * rb + g + 8][8 * ks + t4 + 4];
#pragma unroll
      for (int nt = 0; nt < 8; nt++) {
        uint32_t b0 = Ws[om][8 * nt + g][8 * ks + t4];
        uint32_t b1 = Ws[om][8 * nt + g][8 * ks + t4 + 4];
        mma_tf32(co[nt], a, b0, b1);
      }
    }
  }

  float* dst = (om == 0) ? g_q : (om == 1) ? g_k : g_v;
  const size_t rowbase = ((size_t)b * H + h) * S + (size_t)st * 64 + 16 * rb;
#pragma unroll
  for (int nt = 0; nt < 8; nt++) {
    int col = 8 * nt + 2 * t4;
    *(float2*)&dst[(rowbase + g) * E + col]     = make_float2(co[nt][0], co[nt][1]);
    *(float2*)&dst[(rowbase + g + 8) * E + col] = make_float2(co[nt][2], co[nt][3]);
  }
}

// ---------------------------------------------------------------------------
// Kernel 2: causal flash attention, tf32 MMA, fp32 softmax.
// grid=(S/QR, H, B) with qt reversed (heavy blocks first), block=256 (8 warps).
// Warp w owns query rows [16w, 16w+16) of the 128-row tile, so all row-wise
// softmax reductions stay within the warp's 4-lane groups.
// ---------------------------------------------------------------------------
__global__ __launch_bounds__(256) void attn_mma_kernel(float* __restrict__ out) {
  // smem union: Q staging [128][68] (8704 u32)  /  K^T [64][72] + V [64][72] (9216 u32)
  __shared__ __align__(16) uint32_t sbuf[9216];
  uint32_t (*Qs)[68]  = (uint32_t(*)[68])sbuf;
  uint32_t (*Kst)[72] = (uint32_t(*)[72])sbuf;            // [e][key]
  uint32_t (*Vs)[72]  = (uint32_t(*)[72])(sbuf + 64 * 72); // [key][e]

  const int qt   = (gridDim.x - 1) - blockIdx.x;
  const int h    = blockIdx.y;
  const int b    = blockIdx.z;
  const int tid  = threadIdx.x;
  const int warp = tid >> 5;
  const int lane = tid & 31;
  const int g    = lane >> 2;
  const int t4   = lane & 3;

  const size_t head_base = (((size_t)b * H + h) * S) * E;
  const float* kb = g_k + head_base;
  const float* vb = g_v + head_base;

  // ---- stage Q tile (scaled by 1/8), extract A fragments ----
  {
    const float* qsrc = g_q + head_base + (size_t)qt * QR * E;
#pragma unroll
    for (int i = 0; i < 8; i++) {
      int f  = tid + 256 * i;
      int r  = f >> 4;
      int c4 = f & 15;
      float4 qv = *(const float4*)(qsrc + (size_t)r * E + c4 * 4);
      uint4 u = make_uint4(f2tf32(qv.x * 0.125f), f2tf32(qv.y * 0.125f),
                           f2tf32(qv.z * 0.125f), f2tf32(qv.w * 0.125f));
      *(uint4*)&Qs[r][c4 * 4] = u;
    }
  }
  __syncthreads();

  uint32_t qa[8][4];
  {
    const int r0 = warp * 16 + g;
#pragma unroll
    for (int ks = 0; ks < 8; ks++) {
      qa[ks][0] = Qs[r0][8 * ks + t4];
      qa[ks][1] = Qs[r0 + 8][8 * ks + t4];
      qa[ks][2] = Qs[r0][8 * ks + t4 + 4];
      qa[ks][3] = Qs[r0 + 8][8 * ks + t4 + 4];
    }
  }

  // ---- online softmax state ----
  float o[8][4];
#pragma unroll
  for (int nt = 0; nt < 8; nt++)
#pragma unroll
    for (int i = 0; i < 4; i++) o[nt][i] = 0.f;
  float m0 = -1e30f, m1 = -1e30f, l0 = 0.f, l1 = 0.f;

  const int qrow0w   = qt * QR + warp * 16;  // warp's first query row
  const int rowmax_w = qrow0w + 15;
  const int rg  = qrow0w + g;
  const int rg8 = rg + 8;
  const int kend = (qt + 1) * QR;

  // K load role: e fixed, 4-key column segments
  const int le  = tid & 63;
  const int lj4 = tid >> 6;  // 0..3
  // V load role: row fixed, 4-e segments
  const int vj  = tid >> 2;
  const int ve4 = tid & 3;

  for (int j0 = 0; j0 < kend; j0 += KT) {
    __syncthreads();  // smem reuse barrier (also covers the Q->KV transition)
    // ---- stage K^T [e][key] ----
#pragma unroll
    for (int i = 0; i < 4; i++) {
      int jj4 = lj4 + 4 * i;  // 0..15
      const float* kp = kb + ((size_t)(j0 + 4 * jj4)) * E + le;
      uint4 u = make_uint4(f2tf32(kp[0]), f2tf32(kp[E]), f2tf32(kp[2 * E]),
                           f2tf32(kp[3 * E]));
      *(uint4*)&Kst[le][4 * jj4] = u;
    }
    // ---- stage V [key][e] ----
#pragma unroll
    for (int i = 0; i < 4; i++) {
      int e4 = ve4 + 4 * i;  // 0..15
      float4 vv = *(const float4*)(vb + ((size_t)(j0 + vj)) * E + 4 * e4);
      uint4 u = make_uint4(f2tf32(vv.x), f2tf32(vv.y), f2tf32(vv.z), f2tf32(vv.w));
      *(uint4*)&Vs[vj][4 * e4] = u;
    }
    __syncthreads();

    if (j0 > rowmax_w) continue;  // fully masked for this warp (warp-uniform)

    // ---- S = Q K^T (warp: 16 rows x 64 keys) ----
    float sc[8][4];
#pragma unroll
    for (int nt = 0; nt < 8; nt++)
#pragma unroll
      for (int i = 0; i < 4; i++) sc[nt][i] = 0.f;
#pragma unroll
    for (int ks = 0; ks < 8; ks++) {
#pragma unroll
      for (int nt = 0; nt < 8; nt++) {
        uint32_t b0 = Kst[8 * ks + t4][8 * nt + g];
        uint32_t b1 = Kst[8 * ks + t4 + 4][8 * nt + g];
        mma_tf32(sc[nt], qa[ks], b0, b1);
      }
    }

    // ---- causal mask (only near the diagonal) ----
    if (j0 + KT - 1 > qrow0w) {
      const int colb = j0 + 2 * t4;
#pragma unroll
      for (int nt = 0; nt < 8; nt++) {
        int c0 = colb + 8 * nt;
        if (c0 > rg)      sc[nt][0] = -1e30f;
        if (c0 + 1 > rg)  sc[nt][1] = -1e30f;
        if (c0 > rg8)     sc[nt][2] = -1e30f;
        if (c0 + 1 > rg8) sc[nt][3] = -1e30f;
      }
    }

    // ---- online softmax update ----
    float mx0 = -1e30f, mx1 = -1e30f;
#pragma unroll
    for (int nt = 0; nt < 8; nt++) {
      mx0 = fmaxf(mx0, fmaxf(sc[nt][0], sc[nt][1]));
      mx1 = fmaxf(mx1, fmaxf(sc[nt][2], sc[nt][3]));
    }
    mx0 = fmaxf(mx0, __shfl_xor_sync(0xffffffffu, mx0, 1));
    mx0 = fmaxf(mx0, __shfl_xor_sync(0xffffffffu, mx0, 2));
    mx1 = fmaxf(mx1, __shfl_xor_sync(0xffffffffu, mx1, 1));
    mx1 = fmaxf(mx1, __shfl_xor_sync(0xffffffffu, mx1, 2));

    float mn0 = fmaxf(m0, mx0), mn1 = fmaxf(m1, mx1);
    float corr0 = __expf(m0 - mn0), corr1 = __expf(m1 - mn1);
    m0 = mn0; m1 = mn1;

    float rs0 = 0.f, rs1 = 0.f;
#pragma unroll
    for (int nt = 0; nt < 8; nt++) {
      sc[nt][0] = __expf(sc[nt][0] - mn0);
      sc[nt][1] = __expf(sc[nt][1] - mn0);
      sc[nt][2] = __expf(sc[nt][2] - mn1);
      sc[nt][3] = __expf(sc[nt][3] - mn1);
      rs0 += sc[nt][0] + sc[nt][1];
      rs1 += sc[nt][2] + sc[nt][3];
    }
    l0 = l0 * corr0 + rs0;
    l1 = l1 * corr1 + rs1;
#pragma unroll
    for (int nt = 0; nt < 8; nt++) {
      o[nt][0] *= corr0; o[nt][1] *= corr0;
      o[nt][2] *= corr1; o[nt][3] *= corr1;
    }

    // ---- O += P V ----
    const int s0l = (lane & ~3) | (t4 >> 1);
    const int s2l = s0l + 2;
    const bool odd = (t4 & 1);
#pragma unroll
    for (int ks = 0; ks < 8; ks++) {
      // transpose P chunk (cols 8ks..8ks+7) from C-layout to A-layout
      float v00 = __shfl_sync(0xffffffffu, sc[ks][0], s0l);
      float v01 = __shfl_sync(0xffffffffu, sc[ks][1], s0l);
      float v02 = __shfl_sync(0xffffffffu, sc[ks][2], s0l);
      float v03 = __shfl_sync(0xffffffffu, sc[ks][3], s0l);
      float v20 = __shfl_sync(0xffffffffu, sc[ks][0], s2l);
      float v21 = __shfl_sync(0xffffffffu, sc[ks][1], s2l);
      float v22 = __shfl_sync(0xffffffffu, sc[ks][2], s2l);
      float v23 = __shfl_sync(0xffffffffu, sc[ks][3], s2l);
      uint32_t a[4];
      a[0] = f2tf32(odd ? v01 : v00);
      a[1] = f2tf32(odd ? v03 : v02);
      a[2] = f2tf32(odd ? v21 : v20);
      a[3] = f2tf32(odd ? v23 : v22);
#pragma unroll
      for (int nt = 0; nt < 8; nt++) {
        uint32_t b0 = Vs[8 * ks + t4][8 * nt + g];
        uint32_t b1 = Vs[8 * ks + t4 + 4][8 * nt + g];
        mma_tf32(o[nt], a, b0, b1);
      }
    }
  }

  // ---- finalize: reduce l across 4-lane group, normalize, write [B,S,H*E] ----
  l0 += __shfl_xor_sync(0xffffffffu, l0, 1);
  l0 += __shfl_xor_sync(0xffffffffu, l0, 2);
  l1 += __shfl_xor_sync(0xffffffffu, l1, 1);
  l1 += __shfl_xor_sync(0xffffffffu, l1, 2);
  const float inv0 = 1.f / l0;
  const float inv1 = 1.f / l1;

  float* op0 = out + ((size_t)b * S + rg) * (H * E) + (size_t)h * E;
  float* op8 = out + ((size_t)b * S + rg8) * (H * E) + (size_t)h * E;
#pragma unroll
  for (int nt = 0; nt < 8; nt++) {
    int col = 8 * nt + 2 * t4;
    *(float2*)&op0[col] = make_float2(o[nt][0] * inv0, o[nt][1] * inv0);
    *(float2*)&op8[col] = make_float2(o[nt][2] * inv1, o[nt][3] * inv1);
  }
}

// ---------------------------------------------------------------------------
extern "C" void kernel_launch(void* const* d_in, const int* in_sizes, int n_in,
                              void* d_out, int out_size) {
  const float* x  = (const float*)d_in[0];
  const float* Wq = (const float*)d_in[1];
  const float* Wk = (const float*)d_in[2];
  const float* Wv = (const float*)d_in[3];
  float* out = (float*)d_out;

  dim3 g1(S / 64, H, B);
  qkv_proj_mma<<<g1, 384>>>(x, Wq, Wk, Wv);

  dim3 g2(S / QR, H, B);
  attn_mma_kernel<<<g2, 256>>>(out);
}

// round 5
// speedup vs baseline: 3.2399x; 1.0945x over previous
#include <cuda_runtime.h>
#include <cstdint>

// Problem constants
namespace {
constexpr int B   = 2;
constexpr int S   = 2048;
constexpr int DIN = 1024;
constexpr int H   = 16;
constexpr int E   = 64;

// projection tiles
constexpr int TSP = 128;           // rows per proj block
constexpr int TKP = 16;            // k-chunk
constexpr int NCH = DIN / TKP;     // 64 chunks

// attention tiles
constexpr int QR = 128;            // query rows per attn block
constexpr int KT = 32;             // key tile
}

// Scratch: rounded copies + Q/K/V ([B,H,S,E], pre-rounded tf32 bits; Q pre-scaled)
__device__ float g_xc[(size_t)B * S * DIN];
__device__ float g_wc[(size_t)3 * H * DIN * E];
__device__ float g_q[(size_t)B * H * S * E];
__device__ float g_k[(size_t)B * H * S * E];
__device__ float g_v[(size_t)B * H * S * E];

// ---------------------------------------------------------------------------
// helpers
// ---------------------------------------------------------------------------
__device__ __forceinline__ uint32_t f2tf32(float x) {
  uint32_t r;
  asm("cvt.rna.tf32.f32 %0, %1;" : "=r"(r) : "f"(x));
  return r;
}

__device__ __forceinline__ void mma_tf32(float c[4], const uint32_t a[4],
                                         uint32_t b0, uint32_t b1) {
  asm volatile(
      "mma.sync.aligned.m16n8k8.row.col.f32.tf32.tf32.f32 "
      "{%0,%1,%2,%3}, {%4,%5,%6,%7}, {%8,%9}, {%0,%1,%2,%3};"
      : "+f"(c[0]), "+f"(c[1]), "+f"(c[2]), "+f"(c[3])
      : "r"(a[0]), "r"(a[1]), "r"(a[2]), "r"(a[3]), "r"(b0), "r"(b1));
}

__device__ __forceinline__ void cp16(uint32_t saddr, const void* gaddr) {
  asm volatile("cp.async.ca.shared.global [%0], [%1], 16;" ::"r"(saddr),
               "l"(gaddr));
}
__device__ __forceinline__ void cp_commit() {
  asm volatile("cp.async.commit_group;");
}
__device__ __forceinline__ void cp_wait1() {
  asm volatile("cp.async.wait_group 1;");
}

// ---------------------------------------------------------------------------
// Kernel 0: round fp32 -> tf32-valued fp32 (rna), vectorized
// ---------------------------------------------------------------------------
__global__ __launch_bounds__(256) void cvt_kernel(const float4* __restrict__ src,
                                                  float4* __restrict__ dst,
                                                  int n4) {
  int i = blockIdx.x * blockDim.x + threadIdx.x;
  if (i < n4) {
    float4 v = src[i];
    float4 o;
    o.x = __uint_as_float(f2tf32(v.x));
    o.y = __uint_as_float(f2tf32(v.y));
    o.z = __uint_as_float(f2tf32(v.z));
    o.w = __uint_as_float(f2tf32(v.w));
    dst[i] = o;
  }
}

// ---------------------------------------------------------------------------
// Kernel 1: fused QKV projection, tf32 MMA, cp.async 2-stage pipeline.
// grid=(S/128, H, B), block=384 (12 warps). Warp w: matrix om=w%3, row block
// rb=w/3 (32 rows); each B-fragment feeds 2 MMAs (two 16-row halves).
// ---------------------------------------------------------------------------
__global__ __launch_bounds__(384, 2) void qkv_proj_mma(void) {
  __shared__ __align__(16) uint32_t Xs[2][TSP][20];      // [row][k], stride 20
  __shared__ __align__(16) uint32_t Wsm[2][3][TKP][72];  // [k][n],  stride 72

  const int st   = blockIdx.x;
  const int h    = blockIdx.y;
  const int b    = blockIdx.z;
  const int tid  = threadIdx.x;
  const int warp = tid >> 5;
  const int lane = tid & 31;
  const int g    = lane >> 2;
  const int t4   = lane & 3;
  const int om   = warp % 3;
  const int rb   = warp / 3;

  const float* xb = g_xc + ((size_t)b * S + (size_t)st * TSP) * DIN;

  float co[2][8][4];
#pragma unroll
  for (int h2 = 0; h2 < 2; h2++)
#pragma unroll
    for (int nt = 0; nt < 8; nt++)
#pragma unroll
      for (int i = 0; i < 4; i++) co[h2][nt][i] = 0.f;

  // staging: issue cp.asyncs for chunk s into buffer s&1
  auto stage = [&](int s) {
    const int buf = s & 1;
    const int k0  = s * TKP;
    // X: 128 rows x 16 floats = 128 x 4 segs = 512 tasks
    for (int t = tid; t < 512; t += 384) {
      int r   = t >> 2;
      int seg = t & 3;
      uint32_t d = (uint32_t)__cvta_generic_to_shared(&Xs[buf][r][seg * 4]);
      cp16(d, xb + (size_t)r * DIN + k0 + seg * 4);
    }
    // W: 3 mats x 16 rows x 16 segs = 768 tasks
    for (int t = tid; t < 768; t += 384) {
      int mat = t >> 8;
      int r   = (t >> 4) & 15;
      int seg = t & 15;
      const float* wsrc = g_wc + (size_t)mat * H * DIN * E + (size_t)h * DIN * E;
      uint32_t d = (uint32_t)__cvta_generic_to_shared(&Wsm[buf][mat][r][seg * 4]);
      cp16(d, wsrc + (size_t)(k0 + r) * E + seg * 4);
    }
  };

  stage(0); cp_commit();
  stage(1); cp_commit();

  for (int it = 0; it < NCH; it++) {
    const int buf = it & 1;
    cp_wait1();
    __syncthreads();

#pragma unroll
    for (int ks = 0; ks < 2; ks++) {
      const int kc = 8 * ks + t4;
      uint32_t a[2][4];
#pragma unroll
      for (int h2 = 0; h2 < 2; h2++) {
        const int r0 = 32 * rb + 16 * h2 + g;
        a[h2][0] = Xs[buf][r0][kc];
        a[h2][1] = Xs[buf][r0 + 8][kc];
        a[h2][2] = Xs[buf][r0][kc + 4];
        a[h2][3] = Xs[buf][r0 + 8][kc + 4];
      }
#pragma unroll
      for (int nt = 0; nt < 8; nt++) {
        uint32_t b0 = Wsm[buf][om][8 * ks + t4][8 * nt + g];
        uint32_t b1 = Wsm[buf][om][8 * ks + t4 + 4][8 * nt + g];
        mma_tf32(co[0][nt], a[0], b0, b1);
        mma_tf32(co[1][nt], a[1], b0, b1);
      }
    }

    __syncthreads();
    if (it + 2 < NCH) stage(it + 2);
    cp_commit();
  }

  // store pre-rounded (q pre-scaled by 1/8, exact after rounding)
  float* dst = (om == 0) ? g_q : (om == 1) ? g_k : g_v;
  const float sc = (om == 0) ? 0.125f : 1.0f;
#pragma unroll
  for (int h2 = 0; h2 < 2; h2++) {
    const size_t rowbase =
        ((size_t)b * H + h) * S + (size_t)st * TSP + 32 * rb + 16 * h2;
#pragma unroll
    for (int nt = 0; nt < 8; nt++) {
      int col = 8 * nt + 2 * t4;
      float r00 = __uint_as_float(f2tf32(co[h2][nt][0])) * sc;
      float r01 = __uint_as_float(f2tf32(co[h2][nt][1])) * sc;
      float r10 = __uint_as_float(f2tf32(co[h2][nt][2])) * sc;
      float r11 = __uint_as_float(f2tf32(co[h2][nt][3])) * sc;
      *(float2*)&dst[(rowbase + g) * E + col]     = make_float2(r00, r01);
      *(float2*)&dst[(rowbase + g + 8) * E + col] = make_float2(r10, r11);
    }
  }
}

// ---------------------------------------------------------------------------
// Kernel 2: causal flash attention, tf32 MMA, cp.async 2-stage pipeline.
// grid=(S/QR, H, B) qt reversed, block=256 (8 warps, 16 query rows each).
// K tile [key][e] stride 68 (B-frag reads of K^T conflict-free),
// V tile [key][e] stride 72 (B-frag reads of V conflict-free).
// ---------------------------------------------------------------------------
__global__ __launch_bounds__(256, 2) void attn_mma_kernel(float* __restrict__ out) {
  __shared__ __align__(16) uint32_t Ksm[2][KT][68];
  __shared__ __align__(16) uint32_t Vsm[2][KT][72];

  const int qt   = (gridDim.x - 1) - blockIdx.x;
  const int h    = blockIdx.y;
  const int b    = blockIdx.z;
  const int tid  = threadIdx.x;
  const int warp = tid >> 5;
  const int lane = tid & 31;
  const int g    = lane >> 2;
  const int t4   = lane & 3;

  const size_t head_base = (((size_t)b * H + h) * S) * E;
  const float* kb = g_k + head_base;
  const float* vb = g_v + head_base;

  // Q fragments direct from gmem (pre-rounded, pre-scaled)
  uint32_t qa[8][4];
  {
    const uint32_t* qsrc = (const uint32_t*)(g_q + head_base +
                                             ((size_t)qt * QR + 16 * warp) * E);
#pragma unroll
    for (int ks = 0; ks < 8; ks++) {
      int kc = 8 * ks + t4;
      qa[ks][0] = qsrc[(size_t)g * E + kc];
      qa[ks][1] = qsrc[(size_t)(g + 8) * E + kc];
      qa[ks][2] = qsrc[(size_t)g * E + kc + 4];
      qa[ks][3] = qsrc[(size_t)(g + 8) * E + kc + 4];
    }
  }

  float o[8][4];
#pragma unroll
  for (int nt = 0; nt < 8; nt++)
#pragma unroll
    for (int i = 0; i < 4; i++) o[nt][i] = 0.f;
  float m0 = -1e30f, m1 = -1e30f, l0 = 0.f, l1 = 0.f;

  const int qrow0w   = qt * QR + warp * 16;
  const int rowmax_w = qrow0w + 15;
  const int rg  = qrow0w + g;
  const int rg8 = rg + 8;
  const int n_tiles = ((qt + 1) * QR) / KT;  // >= 4

  auto stage = [&](int s) {
    const int buf = s & 1;
    const int j0  = s * KT;
    // K + V: 2 x (32 rows x 16 segs) = 1024 tasks
    for (int t = tid; t < 1024; t += 256) {
      int mat = t >> 9;
      int r   = (t >> 4) & 31;
      int seg = t & 15;
      if (mat == 0) {
        uint32_t d = (uint32_t)__cvta_generic_to_shared(&Ksm[buf][r][seg * 4]);
        cp16(d, kb + (size_t)(j0 + r) * E + seg * 4);
      } else {
        uint32_t d = (uint32_t)__cvta_generic_to_shared(&Vsm[buf][r][seg * 4]);
        cp16(d, vb + (size_t)(j0 + r) * E + seg * 4);
      }
    }
  };

  stage(0); cp_commit();
  stage(1); cp_commit();

  for (int it = 0; it < n_tiles; it++) {
    const int buf = it & 1;
    const int j0  = it * KT;
    cp_wait1();
    __syncthreads();

    if (j0 <= rowmax_w) {
      // ---- S = Q K^T (16 rows x 32 keys) ----
      float sc[4][4];
#pragma unroll
      for (int nt = 0; nt < 4; nt++)
#pragma unroll
        for (int i = 0; i < 4; i++) sc[nt][i] = 0.f;
#pragma unroll
      for (int ks = 0; ks < 8; ks++) {
#pragma unroll
        for (int nt = 0; nt < 4; nt++) {
          uint32_t b0 = Ksm[buf][8 * nt + g][8 * ks + t4];
          uint32_t b1 = Ksm[buf][8 * nt + g][8 * ks + t4 + 4];
          mma_tf32(sc[nt], qa[ks], b0, b1);
        }
      }

      // ---- causal mask near diagonal ----
      if (j0 + KT - 1 > qrow0w) {
        const int colb = j0 + 2 * t4;
#pragma unroll
        for (int nt = 0; nt < 4; nt++) {
          int c0 = colb + 8 * nt;
          if (c0 > rg)      sc[nt][0] = -1e30f;
          if (c0 + 1 > rg)  sc[nt][1] = -1e30f;
          if (c0 > rg8)     sc[nt][2] = -1e30f;
          if (c0 + 1 > rg8) sc[nt][3] = -1e30f;
        }
      }

      // ---- online softmax ----
      float mx0 = -1e30f, mx1 = -1e30f;
#pragma unroll
      for (int nt = 0; nt < 4; nt++) {
        mx0 = fmaxf(mx0, fmaxf(sc[nt][0], sc[nt][1]));
        mx1 = fmaxf(mx1, fmaxf(sc[nt][2], sc[nt][3]));
      }
      mx0 = fmaxf(mx0, __shfl_xor_sync(0xffffffffu, mx0, 1));
      mx0 = fmaxf(mx0, __shfl_xor_sync(0xffffffffu, mx0, 2));
      mx1 = fmaxf(mx1, __shfl_xor_sync(0xffffffffu, mx1, 1));
      mx1 = fmaxf(mx1, __shfl_xor_sync(0xffffffffu, mx1, 2));

      float mn0 = fmaxf(m0, mx0), mn1 = fmaxf(m1, mx1);
      float corr0 = __expf(m0 - mn0), corr1 = __expf(m1 - mn1);
      m0 = mn0; m1 = mn1;

      float rs0 = 0.f, rs1 = 0.f;
#pragma unroll
      for (int nt = 0; nt < 4; nt++) {
        sc[nt][0] = __expf(sc[nt][0] - mn0);
        sc[nt][1] = __expf(sc[nt][1] - mn0);
        sc[nt][2] = __expf(sc[nt][2] - mn1);
        sc[nt][3] = __expf(sc[nt][3] - mn1);
        rs0 += sc[nt][0] + sc[nt][1];
        rs1 += sc[nt][2] + sc[nt][3];
      }
      l0 = l0 * corr0 + rs0;
      l1 = l1 * corr1 + rs1;
#pragma unroll
      for (int nt = 0; nt < 8; nt++) {
        o[nt][0] *= corr0; o[nt][1] *= corr0;
        o[nt][2] *= corr1; o[nt][3] *= corr1;
      }

      // ---- O += P V ----
      const int s0l = (lane & ~3) | (t4 >> 1);
      const int s2l = s0l + 2;
      const bool odd = (t4 & 1);
#pragma unroll
      for (int ks = 0; ks < 4; ks++) {
        float v00 = __shfl_sync(0xffffffffu, sc[ks][0], s0l);
        float v01 = __shfl_sync(0xffffffffu, sc[ks][1], s0l);
        float v02 = __shfl_sync(0xffffffffu, sc[ks][2], s0l);
        float v03 = __shfl_sync(0xffffffffu, sc[ks][3], s0l);
        float v20 = __shfl_sync(0xffffffffu, sc[ks][0], s2l);
        float v21 = __shfl_sync(0xffffffffu, sc[ks][1], s2l);
        float v22 = __shfl_sync(0xffffffffu, sc[ks][2], s2l);
        float v23 = __shfl_sync(0xffffffffu, sc[ks][3], s2l);
        uint32_t a[4];
        a[0] = f2tf32(odd ? v01 : v00);
        a[1] = f2tf32(odd ? v03 : v02);
        a[2] = f2tf32(odd ? v21 : v20);
        a[3] = f2tf32(odd ? v23 : v22);
#pragma unroll
        for (int nt = 0; nt < 8; nt++) {
          uint32_t b0 = Vsm[buf][8 * ks + t4][8 * nt + g];
          uint32_t b1 = Vsm[buf][8 * ks + t4 + 4][8 * nt + g];
          mma_tf32(o[nt], a, b0, b1);
        }
      }
    }

    __syncthreads();
    if (it + 2 < n_tiles) stage(it + 2);
    cp_commit();
  }

  // ---- finalize ----
  l0 += __shfl_xor_sync(0xffffffffu, l0, 1);
  l0 += __shfl_xor_sync(0xffffffffu, l0, 2);
  l1 += __shfl_xor_sync(0xffffffffu, l1, 1);
  l1 += __shfl_xor_sync(0xffffffffu, l1, 2);
  const float inv0 = 1.f / l0;
  const float inv1 = 1.f / l1;

  float* op0 = out + ((size_t)b * S + rg) * (H * E) + (size_t)h * E;
  float* op8 = out + ((size_t)b * S + rg8) * (H * E) + (size_t)h * E;
#pragma unroll
  for (int nt = 0; nt < 8; nt++) {
    int col = 8 * nt + 2 * t4;
    *(float2*)&op0[col] = make_float2(o[nt][0] * inv0, o[nt][1] * inv0);
    *(float2*)&op8[col] = make_float2(o[nt][2] * inv1, o[nt][3] * inv1);
  }
}

// ---------------------------------------------------------------------------
extern "C" void kernel_launch(void* const* d_in, const int* in_sizes, int n_in,
                              void* d_out, int out_size) {
  const float* x  = (const float*)d_in[0];
  const float* Wq = (const float*)d_in[1];
  const float* Wk = (const float*)d_in[2];
  const float* Wv = (const float*)d_in[3];
  float* out = (float*)d_out;

  // resolve device scratch addresses (host-side; cached by CUDA runtime)
  float *xc, *wc;
  cudaGetSymbolAddress((void**)&xc, g_xc);
  cudaGetSymbolAddress((void**)&wc, g_wc);

  const int nx4 = B * S * DIN / 4;          // 1,048,576
  const int nw4 = H * DIN * E / 4;          // 262,144
  cvt_kernel<<<(nx4 + 255) / 256, 256>>>((const float4*)x, (float4*)xc, nx4);
  cvt_kernel<<<(nw4 + 255) / 256, 256>>>((const float4*)Wq, (float4*)(wc + 0 * (size_t)H * DIN * E), nw4);
  cvt_kernel<<<(nw4 + 255) / 256, 256>>>((const float4*)Wk, (float4*)(wc + 1 * (size_t)H * DIN * E), nw4);
  cvt_kernel<<<(nw4 + 255) / 256, 256>>>((const float4*)Wv, (float4*)(wc + 2 * (size_t)H * DIN * E), nw4);

  dim3 g1(S / TSP, H, B);
  qkv_proj_mma<<<g1, 384>>>();

  dim3 g2(S / QR, H, B);
  attn_mma_kernel<<<g2, 256>>>(out);
}

// round 6
// speedup vs baseline: 3.3869x; 1.0454x over previous
#include <cuda_runtime.h>
#include <cstdint>

// Problem constants
namespace {
constexpr int B   = 2;
constexpr int S   = 2048;
constexpr int DIN = 1024;
constexpr int H   = 16;
constexpr int E   = 64;

// projection tiles
constexpr int TSP = 128;           // rows per proj block
constexpr int TKP = 16;            // k-chunk
constexpr int NCH = DIN / TKP;     // 64 chunks

// attention tiles
constexpr int QR = 128;            // query rows per attn block
constexpr int KT = 32;             // key tile
}

// Scratch: rounded x, rounded+transposed W ([mat][h][e][din]), Q/K/V [B,H,S,E]
__device__ float g_xc[(size_t)B * S * DIN];
__device__ float g_wt[(size_t)3 * H * E * DIN];
__device__ float g_q[(size_t)B * H * S * E];
__device__ float g_k[(size_t)B * H * S * E];
__device__ float g_v[(size_t)B * H * S * E];

// ---------------------------------------------------------------------------
// helpers
// ---------------------------------------------------------------------------
__device__ __forceinline__ uint32_t f2tf32(float x) {
  uint32_t r;
  asm("cvt.rna.tf32.f32 %0, %1;" : "=r"(r) : "f"(x));
  return r;
}

__device__ __forceinline__ void mma_tf32(float c[4], const uint32_t a[4],
                                         uint32_t b0, uint32_t b1) {
  asm volatile(
      "mma.sync.aligned.m16n8k8.row.col.f32.tf32.tf32.f32 "
      "{%0,%1,%2,%3}, {%4,%5,%6,%7}, {%8,%9}, {%0,%1,%2,%3};"
      : "+f"(c[0]), "+f"(c[1]), "+f"(c[2]), "+f"(c[3])
      : "r"(a[0]), "r"(a[1]), "r"(a[2]), "r"(a[3]), "r"(b0), "r"(b1));
}

#define LDSM4(d0, d1, d2, d3, addr)                                       \
  asm volatile(                                                           \
      "ldmatrix.sync.aligned.m8n8.x4.shared.b16 {%0,%1,%2,%3}, [%4];"     \
      : "=r"(d0), "=r"(d1), "=r"(d2), "=r"(d3)                            \
      : "r"(addr))

__device__ __forceinline__ void cp16(uint32_t saddr, const void* gaddr) {
  asm volatile("cp.async.ca.shared.global [%0], [%1], 16;" ::"r"(saddr),
               "l"(gaddr));
}
__device__ __forceinline__ void cp_commit() {
  asm volatile("cp.async.commit_group;");
}
__device__ __forceinline__ void cp_wait1() {
  asm volatile("cp.async.wait_group 1;");
}

// ---------------------------------------------------------------------------
// Kernel 0a: round x fp32 -> tf32-valued fp32 (rna), vectorized
// ---------------------------------------------------------------------------
__global__ __launch_bounds__(256) void cvt_kernel(const float4* __restrict__ src,
                                                  float4* __restrict__ dst,
                                                  int n4) {
  int i = blockIdx.x * blockDim.x + threadIdx.x;
  if (i < n4) {
    float4 v = src[i];
    float4 o;
    o.x = __uint_as_float(f2tf32(v.x));
    o.y = __uint_as_float(f2tf32(v.y));
    o.z = __uint_as_float(f2tf32(v.z));
    o.w = __uint_as_float(f2tf32(v.w));
    dst[i] = o;
  }
}

// ---------------------------------------------------------------------------
// Kernel 0b: W -> W^T per (mat,head), rounded. grid(DIN/32, E/32, 3H),
// block(32,8). g_wt[mat][h][e][din].
// ---------------------------------------------------------------------------
__global__ __launch_bounds__(256) void cvtw_kernel(const float* __restrict__ Wq,
                                                   const float* __restrict__ Wk,
                                                   const float* __restrict__ Wv) {
  __shared__ float t[32][33];
  const int mat = blockIdx.z / H;
  const int h   = blockIdx.z % H;
  const int k0  = blockIdx.x * 32;
  const int e0  = blockIdx.y * 32;
  const int tx  = threadIdx.x;
  const int ty  = threadIdx.y;
  const float* src =
      ((mat == 0) ? Wq : (mat == 1) ? Wk : Wv) + (size_t)h * DIN * E;
#pragma unroll
  for (int i = 0; i < 4; i++)
    t[ty + 8 * i][tx] = src[(size_t)(k0 + ty + 8 * i) * E + e0 + tx];
  __syncthreads();
  float* dst = g_wt + (((size_t)mat * H + h) * E) * DIN;
#pragma unroll
  for (int i = 0; i < 4; i++)
    dst[(size_t)(e0 + ty + 8 * i) * DIN + k0 + tx] =
        __uint_as_float(f2tf32(t[tx][ty + 8 * i]));
}

// ---------------------------------------------------------------------------
// Kernel 1: fused QKV projection, tf32 MMA + ldmatrix, cp.async pipeline.
// grid=(S/128, H, B), block=384 (12 warps): warp = matrix (w%3) x 32-row
// block (w/3). Dynamic smem: Xs[2][128][20] + Ws[2][3][64][20] (W^T [n][k]).
// ---------------------------------------------------------------------------
__global__ __launch_bounds__(384, 2) void qkv_proj_mma(void) {
  extern __shared__ __align__(16) uint32_t dsm[];
  uint32_t (*Xs)[TSP][20]   = (uint32_t(*)[TSP][20])dsm;            // [2]
  uint32_t (*Ws)[3][64][20] = (uint32_t(*)[3][64][20])(dsm + 2 * TSP * 20);

  const int st   = blockIdx.x;
  const int h    = blockIdx.y;
  const int b    = blockIdx.z;
  const int tid  = threadIdx.x;
  const int warp = tid >> 5;
  const int lane = tid & 31;
  const int g    = lane >> 2;
  const int t4   = lane & 3;
  const int om   = warp % 3;
  const int rb   = warp / 3;

  const float* xb = g_xc + ((size_t)b * S + (size_t)st * TSP) * DIN;
  const float* wt = g_wt + (size_t)h * E * DIN;  // + mat*H*E*DIN

  float co[2][8][4];
#pragma unroll
  for (int h2 = 0; h2 < 2; h2++)
#pragma unroll
    for (int nt = 0; nt < 8; nt++)
#pragma unroll
      for (int i = 0; i < 4; i++) co[h2][nt][i] = 0.f;

  // ldmatrix base addresses (shared space)
  const int arow = 32 * rb + (lane & 15);
  const int acol = 4 * (lane >> 4);
  const int brow = (lane & 7) + ((lane & 16) >> 1);
  const int bcol = (lane & 8) >> 1;
  uint32_t uA[2], uB[2];
#pragma unroll
  for (int buf = 0; buf < 2; buf++) {
    uA[buf] = (uint32_t)__cvta_generic_to_shared(&Xs[buf][arow][acol]);
    uB[buf] = (uint32_t)__cvta_generic_to_shared(&Ws[buf][om][brow][bcol]);
  }

  auto stage = [&](int s) {
    const int buf = s & 1;
    const int k0  = s * TKP;
    // X: 128 rows x 4 segs
    for (int t = tid; t < 512; t += 384) {
      int r   = t >> 2;
      int seg = t & 3;
      uint32_t d = (uint32_t)__cvta_generic_to_shared(&Xs[buf][r][seg * 4]);
      cp16(d, xb + (size_t)r * DIN + k0 + seg * 4);
    }
    // W^T: 3 mats x 64 n-rows x 4 segs
    for (int t = tid; t < 768; t += 384) {
      int mat = t >> 8;
      int n   = (t >> 2) & 63;
      int seg = t & 3;
      uint32_t d = (uint32_t)__cvta_generic_to_shared(&Ws[buf][mat][n][seg * 4]);
      cp16(d, wt + (size_t)mat * H * E * DIN + (size_t)n * DIN + k0 + seg * 4);
    }
  };

  stage(0); cp_commit();
  stage(1); cp_commit();

  for (int it = 0; it < NCH; it++) {
    const int buf = it & 1;
    cp_wait1();
    __syncthreads();

#pragma unroll
    for (int ks = 0; ks < 2; ks++) {
      uint32_t a[2][4];
#pragma unroll
      for (int h2 = 0; h2 < 2; h2++)
        LDSM4(a[h2][0], a[h2][1], a[h2][2], a[h2][3],
              uA[buf] + (16 * h2 * 20 + 8 * ks) * 4);
#pragma unroll
      for (int ntp = 0; ntp < 4; ntp++) {
        uint32_t b0, b1, b2, b3;
        LDSM4(b0, b1, b2, b3, uB[buf] + (16 * ntp * 20 + 8 * ks) * 4);
        mma_tf32(co[0][2 * ntp],     a[0], b0, b1);
        mma_tf32(co[0][2 * ntp + 1], a[0], b2, b3);
        mma_tf32(co[1][2 * ntp],     a[1], b0, b1);
        mma_tf32(co[1][2 * ntp + 1], a[1], b2, b3);
      }
    }

    __syncthreads();
    if (it + 2 < NCH) stage(it + 2);
    cp_commit();
  }

  // store pre-rounded (q pre-scaled by 1/8, exact after rounding)
  float* dst = (om == 0) ? g_q : (om == 1) ? g_k : g_v;
  const float sc = (om == 0) ? 0.125f : 1.0f;
#pragma unroll
  for (int h2 = 0; h2 < 2; h2++) {
    const size_t rowbase =
        ((size_t)b * H + h) * S + (size_t)st * TSP + 32 * rb + 16 * h2;
#pragma unroll
    for (int nt = 0; nt < 8; nt++) {
      int col = 8 * nt + 2 * t4;
      float r00 = __uint_as_float(f2tf32(co[h2][nt][0])) * sc;
      float r01 = __uint_as_float(f2tf32(co[h2][nt][1])) * sc;
      float r10 = __uint_as_float(f2tf32(co[h2][nt][2])) * sc;
      float r11 = __uint_as_float(f2tf32(co[h2][nt][3])) * sc;
      *(float2*)&dst[(rowbase + g) * E + col]     = make_float2(r00, r01);
      *(float2*)&dst[(rowbase + g + 8) * E + col] = make_float2(r10, r11);
    }
  }
}

// ---------------------------------------------------------------------------
// Kernel 2: causal flash attention, tf32 MMA + ldmatrix(K), cp.async pipeline.
// grid=(S/QR, H, B) qt reversed, block=256 (8 warps, 16 query rows each).
// Ksm [key][e] stride 68 (LDSM-friendly), Vsm [key][e] stride 72 (scalar,
// conflict-free for the V B-frag pattern).
// ---------------------------------------------------------------------------
__global__ __launch_bounds__(256, 2) void attn_mma_kernel(float* __restrict__ out) {
  __shared__ __align__(16) uint32_t Ksm[2][KT][68];
  __shared__ __align__(16) uint32_t Vsm[2][KT][72];

  const int qt   = (gridDim.x - 1) - blockIdx.x;
  const int h    = blockIdx.y;
  const int b    = blockIdx.z;
  const int tid  = threadIdx.x;
  const int warp = tid >> 5;
  const int lane = tid & 31;
  const int g    = lane >> 2;
  const int t4   = lane & 3;

  const size_t head_base = (((size_t)b * H + h) * S) * E;
  const float* kb = g_k + head_base;
  const float* vb = g_v + head_base;

  // Q fragments direct from gmem (pre-rounded, pre-scaled)
  uint32_t qa[8][4];
  {
    const uint32_t* qsrc = (const uint32_t*)(g_q + head_base +
                                             ((size_t)qt * QR + 16 * warp) * E);
#pragma unroll
    for (int ks = 0; ks < 8; ks++) {
      int kc = 8 * ks + t4;
      qa[ks][0] = qsrc[(size_t)g * E + kc];
      qa[ks][1] = qsrc[(size_t)(g + 8) * E + kc];
      qa[ks][2] = qsrc[(size_t)g * E + kc + 4];
      qa[ks][3] = qsrc[(size_t)(g + 8) * E + kc + 4];
    }
  }

  // ldmatrix base addresses for K
  const int brow = (lane & 7) + ((lane & 16) >> 1);
  const int bcol = (lane & 8) >> 1;
  uint32_t uK[2];
#pragma unroll
  for (int buf = 0; buf < 2; buf++)
    uK[buf] = (uint32_t)__cvta_generic_to_shared(&Ksm[buf][brow][bcol]);

  float o[8][4];
#pragma unroll
  for (int nt = 0; nt < 8; nt++)
#pragma unroll
    for (int i = 0; i < 4; i++) o[nt][i] = 0.f;
  float m0 = -1e30f, m1 = -1e30f, l0 = 0.f, l1 = 0.f;

  const int qrow0w   = qt * QR + warp * 16;
  const int rowmax_w = qrow0w + 15;
  const int rg  = qrow0w + g;
  const int rg8 = rg + 8;
  const int n_tiles = ((qt + 1) * QR) / KT;  // >= 4

  auto stage = [&](int s) {
    const int buf = s & 1;
    const int j0  = s * KT;
    for (int t = tid; t < 1024; t += 256) {
      int mat = t >> 9;
      int r   = (t >> 4) & 31;
      int seg = t & 15;
      if (mat == 0) {
        uint32_t d = (uint32_t)__cvta_generic_to_shared(&Ksm[buf][r][seg * 4]);
        cp16(d, kb + (size_t)(j0 + r) * E + seg * 4);
      } else {
        uint32_t d = (uint32_t)__cvta_generic_to_shared(&Vsm[buf][r][seg * 4]);
        cp16(d, vb + (size_t)(j0 + r) * E + seg * 4);
      }
    }
  };

  stage(0); cp_commit();
  stage(1); cp_commit();

  for (int it = 0; it < n_tiles; it++) {
    const int buf = it & 1;
    const int j0  = it * KT;
    cp_wait1();
    __syncthreads();

    if (j0 <= rowmax_w) {
      // ---- S = Q K^T (16 rows x 32 keys) ----
      float sc[4][4];
#pragma unroll
      for (int nt = 0; nt < 4; nt++)
#pragma unroll
        for (int i = 0; i < 4; i++) sc[nt][i] = 0.f;
#pragma unroll
      for (int ks = 0; ks < 8; ks++) {
#pragma unroll
        for (int ntp = 0; ntp < 2; ntp++) {
          uint32_t b0, b1, b2, b3;
          LDSM4(b0, b1, b2, b3, uK[buf] + (16 * ntp * 68 + 8 * ks) * 4);
          mma_tf32(sc[2 * ntp],     qa[ks], b0, b1);
          mma_tf32(sc[2 * ntp + 1], qa[ks], b2, b3);
        }
      }

      // ---- causal mask near diagonal ----
      if (j0 + KT - 1 > qrow0w) {
        const int colb = j0 + 2 * t4;
#pragma unroll
        for (int nt = 0; nt < 4; nt++) {
          int c0 = colb + 8 * nt;
          if (c0 > rg)      sc[nt][0] = -1e30f;
          if (c0 + 1 > rg)  sc[nt][1] = -1e30f;
          if (c0 > rg8)     sc[nt][2] = -1e30f;
          if (c0 + 1 > rg8) sc[nt][3] = -1e30f;
        }
      }

      // ---- online softmax ----
      float mx0 = -1e30f, mx1 = -1e30f;
#pragma unroll
      for (int nt = 0; nt < 4; nt++) {
        mx0 = fmaxf(mx0, fmaxf(sc[nt][0], sc[nt][1]));
        mx1 = fmaxf(mx1, fmaxf(sc[nt][2], sc[nt][3]));
      }
      mx0 = fmaxf(mx0, __shfl_xor_sync(0xffffffffu, mx0, 1));
      mx0 = fmaxf(mx0, __shfl_xor_sync(0xffffffffu, mx0, 2));
      mx1 = fmaxf(mx1, __shfl_xor_sync(0xffffffffu, mx1, 1));
      mx1 = fmaxf(mx1, __shfl_xor_sync(0xffffffffu, mx1, 2));

      float mn0 = fmaxf(m0, mx0), mn1 = fmaxf(m1, mx1);
      float corr0 = __expf(m0 - mn0), corr1 = __expf(m1 - mn1);
      m0 = mn0; m1 = mn1;

      float rs0 = 0.f, rs1 = 0.f;
#pragma unroll
      for (int nt = 0; nt < 4; nt++) {
        sc[nt][0] = __expf(sc[nt][0] - mn0);
        sc[nt][1] = __expf(sc[nt][1] - mn0);
        sc[nt][2] = __expf(sc[nt][2] - mn1);
        sc[nt][3] = __expf(sc[nt][3] - mn1);
        rs0 += sc[nt][0] + sc[nt][1];
        rs1 += sc[nt][2] + sc[nt][3];
      }
      l0 = l0 * corr0 + rs0;
      l1 = l1 * corr1 + rs1;
#pragma unroll
      for (int nt = 0; nt < 8; nt++) {
        o[nt][0] *= corr0; o[nt][1] *= corr0;
        o[nt][2] *= corr1; o[nt][3] *= corr1;
      }

      // ---- O += P V ----
      const int s0l = (lane & ~3) | (t4 >> 1);
      const int s2l = s0l + 2;
      const bool odd = (t4 & 1);
#pragma unroll
      for (int ks = 0; ks < 4; ks++) {
        float v00 = __shfl_sync(0xffffffffu, sc[ks][0], s0l);
        float v01 = __shfl_sync(0xffffffffu, sc[ks][1], s0l);
        float v02 = __shfl_sync(0xffffffffu, sc[ks][2], s0l);
        float v03 = __shfl_sync(0xffffffffu, sc[ks][3], s0l);
        float v20 = __shfl_sync(0xffffffffu, sc[ks][0], s2l);
        float v21 = __shfl_sync(0xffffffffu, sc[ks][1], s2l);
        float v22 = __shfl_sync(0xffffffffu, sc[ks][2], s2l);
        float v23 = __shfl_sync(0xffffffffu, sc[ks][3], s2l);
        uint32_t a[4];
        a[0] = f2tf32(odd ? v01 : v00);
        a[1] = f2tf32(odd ? v03 : v02);
        a[2] = f2tf32(odd ? v21 : v20);
        a[3] = f2tf32(odd ? v23 : v22);
#pragma unroll
        for (int nt = 0; nt < 8; nt++) {
          uint32_t b0 = Vsm[buf][8 * ks + t4][8 * nt + g];
          uint32_t b1 = Vsm[buf][8 * ks + t4 + 4][8 * nt + g];
          mma_tf32(o[nt], a, b0, b1);
        }
      }
    }

    __syncthreads();
    if (it + 2 < n_tiles) stage(it + 2);
    cp_commit();
  }

  // ---- finalize ----
  l0 += __shfl_xor_sync(0xffffffffu, l0, 1);
  l0 += __shfl_xor_sync(0xffffffffu, l0, 2);
  l1 += __shfl_xor_sync(0xffffffffu, l1, 1);
  l1 += __shfl_xor_sync(0xffffffffu, l1, 2);
  const float inv0 = 1.f / l0;
  const float inv1 = 1.f / l1;

  float* op0 = out + ((size_t)b * S + rg) * (H * E) + (size_t)h * E;
  float* op8 = out + ((size_t)b * S + rg8) * (H * E) + (size_t)h * E;
#pragma unroll
  for (int nt = 0; nt < 8; nt++) {
    int col = 8 * nt + 2 * t4;
    *(float2*)&op0[col] = make_float2(o[nt][0] * inv0, o[nt][1] * inv0);
    *(float2*)&op8[col] = make_float2(o[nt][2] * inv1, o[nt][3] * inv1);
  }
}

// ---------------------------------------------------------------------------
extern "C" void kernel_launch(void* const* d_in, const int* in_sizes, int n_in,
                              void* d_out, int out_size) {
  const float* x  = (const float*)d_in[0];
  const float* Wq = (const float*)d_in[1];
  const float* Wk = (const float*)d_in[2];
  const float* Wv = (const float*)d_in[3];
  float* out = (float*)d_out;

  float* xc;
  cudaGetSymbolAddress((void**)&xc, g_xc);

  const int nx4 = B * S * DIN / 4;
  cvt_kernel<<<(nx4 + 255) / 256, 256>>>((const float4*)x, (float4*)xc, nx4);

  dim3 gw(DIN / 32, E / 32, 3 * H);
  cvtw_kernel<<<gw, dim3(32, 8)>>>(Wq, Wk, Wv);

  const int proj_smem = (2 * TSP * 20 + 2 * 3 * 64 * 20) * 4;  // 51200 B
  cudaFuncSetAttribute(qkv_proj_mma, cudaFuncAttributeMaxDynamicSharedMemorySize,
                       proj_smem);
  dim3 g1(S / TSP, H, B);
  qkv_proj_mma<<<g1, 384, proj_smem>>>();

  dim3 g2(S / QR, H, B);
  attn_mma_kernel<<<g2, 256>>>(out);
}